// round 14
// baseline (speedup 1.0000x reference)
#include <cuda_runtime.h>

#define C 64
#define MAXN 50000
#define MAXE 800000
#define LN_EPS 1e-5f
#define GN_EPS 1e-5f

// Scratch (no allocs allowed)
__device__ float g_agg[(size_t)MAXN * C];
__device__ float g_h2[(size_t)MAXN * C];
__device__ float g_S1[C];
__device__ float g_S2[C];

// ---------------------------------------------------------------------------
// f32x2 packed-FMA helpers (sm_100+)
// ---------------------------------------------------------------------------
__device__ __forceinline__ unsigned long long pk(float x, float y) {
    unsigned long long r;
    asm("mov.b64 %0, {%1, %2};" : "=l"(r) : "f"(x), "f"(y));
    return r;
}
__device__ __forceinline__ void upk(unsigned long long p, float& x, float& y) {
    asm("mov.b64 {%0, %1}, %2;" : "=f"(x), "=f"(y) : "l"(p));
}
__device__ __forceinline__ unsigned long long f2fma(unsigned long long a,
                                                    unsigned long long b,
                                                    unsigned long long c) {
    unsigned long long d;
    asm("fma.rn.f32x2 %0, %1, %2, %3;" : "=l"(d) : "l"(a), "l"(b), "l"(c));
    return d;
}

// ---------------------------------------------------------------------------
// K0: agg = x (GIN self term), zero stats. Two float4 per thread, one-shot.
// ---------------------------------------------------------------------------
__global__ __launch_bounds__(256) void k_init(
        const float4* __restrict__ x4, float4* __restrict__ agg4,
        long long n4, float* s1, float* s2) {
    long long base = (long long)blockIdx.x * 512 + threadIdx.x;
    if (base < n4)       agg4[base] = x4[base];
    if (base + 256 < n4) agg4[base + 256] = x4[base + 256];
    long long i = (long long)blockIdx.x * blockDim.x + threadIdx.x;
    if (i < C) { s1[i] = 0.f; s2[i] = 0.f; }
}

// ---------------------------------------------------------------------------
// edge_index dtype sniff (JAX x64-disable silently narrows int64 -> int32)
// ---------------------------------------------------------------------------
__device__ __forceinline__ bool ei_is_int64(const long long* ei, int N) {
    bool ok = true;
    #pragma unroll
    for (int i = 0; i < 4; i++) {
        long long v = __ldg(ei + i);
        ok = ok && (v >= 0) && (v < (long long)N);
    }
    return ok;
}

// ---------------------------------------------------------------------------
// K1: scatter-add   agg[dst] += x[src]   (16 threads/edge, float4 vector red)
// ---------------------------------------------------------------------------
__global__ void k_scatter(const float* __restrict__ x,
                          const long long* __restrict__ ei,
                          float* __restrict__ agg, int E, int N) {
    long long tid = (long long)blockIdx.x * blockDim.x + threadIdx.x;
    int e = (int)(tid >> 4);
    if (e >= E) return;
    int g = (int)(tid & 15);

    int s, d;
    if (ei_is_int64(ei, N)) {
        s = (int)__ldg(ei + e);
        d = (int)__ldg(ei + (long long)E + e);
    } else {
        const int* ei32 = (const int*)ei;
        s = __ldg(ei32 + e);
        d = __ldg(ei32 + (long long)E + e);
    }
    if ((unsigned)s >= (unsigned)N || (unsigned)d >= (unsigned)N) return;

    float4 v = __ldg((const float4*)(x + (long long)s * C) + g);
    float4* a4 = (float4*)(agg + (long long)d * C) + g;
    atomicAdd(a4, v);   // RED.E.ADD.V4.F32
}

// ---------------------------------------------------------------------------
// K2: MLP, 16 nodes/warp, f32x2 packed FMA with PRE-DUPLICATED weights
//     (no per-iteration dup MOVs on the fma pipe), 96KB dynamic smem,
//     persistent, fused GN partials.
// ---------------------------------------------------------------------------
__global__ __launch_bounds__(256, 2) void k_mlp(
    const float* __restrict__ agg,
    const float* __restrict__ W0, const float* __restrict__ ln0w, const float* __restrict__ ln0b,
    const float* __restrict__ W1, const float* __restrict__ ln1w, const float* __restrict__ ln1b,
    float* __restrict__ h2, float* __restrict__ S1, float* __restrict__ S2, int N) {

    extern __shared__ char dsm[];
    // layout: W0x 16KB | W0y 16KB | W1x 16KB | W1y 16KB | shbA..D 4x8KB = 96KB
    unsigned long long* sW0x = (unsigned long long*)dsm;              // [2048]
    unsigned long long* sW0y = (unsigned long long*)(dsm + 16384);
    unsigned long long* sW1x = (unsigned long long*)(dsm + 32768);
    unsigned long long* sW1y = (unsigned long long*)(dsm + 49152);
    ulonglong2 (*shbA)[64] = (ulonglong2(*)[64])(dsm + 65536);
    ulonglong2 (*shbB)[64] = (ulonglong2(*)[64])(dsm + 73728);
    ulonglong2 (*shbC)[64] = (ulonglong2(*)[64])(dsm + 81920);
    ulonglong2 (*shbD)[64] = (ulonglong2(*)[64])(dsm + 90112);
    float* sS = (float*)(dsm + 65536);   // aliased stats staging (post-loop)

    int tid = threadIdx.x;
    for (int i = tid; i < 2048; i += 256) {
        int k = i >> 5, l = i & 31;
        float w0a = W0[l * 64 + k], w0b = W0[(l + 32) * 64 + k];
        float w1a = W1[l * 64 + k], w1b = W1[(l + 32) * 64 + k];
        sW0x[i] = pk(w0a, w0a);
        sW0y[i] = pk(w0b, w0b);
        sW1x[i] = pk(w1a, w1a);
        sW1y[i] = pk(w1b, w1b);
    }
    __syncthreads();

    int w = tid >> 5, l = tid & 31;
    float p0w = __ldg(ln0w + l),      p0b = __ldg(ln0b + l);
    float p1w = __ldg(ln0w + l + 32), p1b = __ldg(ln0b + l + 32);
    float q0w = __ldg(ln1w + l),      q0b = __ldg(ln1b + l);
    float q1w = __ldg(ln1w + l + 32), q1b = __ldg(ln1b + l + 32);

    float accS1_0 = 0.f, accS1_1 = 0.f, accS2_0 = 0.f, accS2_1 = 0.f;
    const unsigned long long Z = 0ull;

    int groups = (N + 127) >> 7;         // 128 nodes per block-iteration
    for (int gi = blockIdx.x; gi < groups; gi += gridDim.x) {
        int nbase = gi * 128 + w * 16;

        // ---- load h (16 nodes) + stage into shared ----
        {
            float h0[16], h1[16];
            #pragma unroll
            for (int j = 0; j < 16; j++) {
                int n = nbase + j;
                if (n < N) {
                    long long b = (long long)n * C;
                    h0[j] = agg[b + l];
                    h1[j] = agg[b + 32 + l];
                } else { h0[j] = 0.f; h1[j] = 0.f; }
            }
            shbA[w][l]      = make_ulonglong2(pk(h0[0],  h0[1]),  pk(h0[2],  h0[3]));
            shbB[w][l]      = make_ulonglong2(pk(h0[4],  h0[5]),  pk(h0[6],  h0[7]));
            shbC[w][l]      = make_ulonglong2(pk(h0[8],  h0[9]),  pk(h0[10], h0[11]));
            shbD[w][l]      = make_ulonglong2(pk(h0[12], h0[13]), pk(h0[14], h0[15]));
            shbA[w][l + 32] = make_ulonglong2(pk(h1[0],  h1[1]),  pk(h1[2],  h1[3]));
            shbB[w][l + 32] = make_ulonglong2(pk(h1[4],  h1[5]),  pk(h1[6],  h1[7]));
            shbC[w][l + 32] = make_ulonglong2(pk(h1[8],  h1[9]),  pk(h1[10], h1[11]));
            shbD[w][l + 32] = make_ulonglong2(pk(h1[12], h1[13]), pk(h1[14], h1[15]));
        }
        __syncwarp();

        // ---- GEMM1 ----
        unsigned long long accL[8], accH[8];
        #pragma unroll
        for (int i = 0; i < 8; i++) { accL[i] = Z; accH[i] = Z; }
        #pragma unroll
        for (int k = 0; k < 64; k++) {
            ulonglong2 hA = shbA[w][k];
            ulonglong2 hB = shbB[w][k];
            ulonglong2 hC = shbC[w][k];
            ulonglong2 hD = shbD[w][k];
            unsigned long long wxx = sW0x[k * 32 + l];
            unsigned long long wyy = sW0y[k * 32 + l];
            accL[0] = f2fma(hA.x, wxx, accL[0]); accH[0] = f2fma(hA.x, wyy, accH[0]);
            accL[1] = f2fma(hA.y, wxx, accL[1]); accH[1] = f2fma(hA.y, wyy, accH[1]);
            accL[2] = f2fma(hB.x, wxx, accL[2]); accH[2] = f2fma(hB.x, wyy, accH[2]);
            accL[3] = f2fma(hB.y, wxx, accL[3]); accH[3] = f2fma(hB.y, wyy, accH[3]);
            accL[4] = f2fma(hC.x, wxx, accL[4]); accH[4] = f2fma(hC.x, wyy, accH[4]);
            accL[5] = f2fma(hC.y, wxx, accL[5]); accH[5] = f2fma(hC.y, wyy, accH[5]);
            accL[6] = f2fma(hD.x, wxx, accL[6]); accH[6] = f2fma(hD.x, wyy, accH[6]);
            accL[7] = f2fma(hD.y, wxx, accL[7]); accH[7] = f2fma(hD.y, wyy, accH[7]);
        }
        float o0[16], o1[16];
        #pragma unroll
        for (int i = 0; i < 8; i++) {
            upk(accL[i], o0[2 * i], o0[2 * i + 1]);
            upk(accH[i], o1[2 * i], o1[2 * i + 1]);
        }

        // ---- LN0 + ReLU (16 nodes) ----
        {
            float s[16], q[16];
            #pragma unroll
            for (int j = 0; j < 16; j++) {
                s[j] = o0[j] + o1[j];
                q[j] = o0[j] * o0[j] + o1[j] * o1[j];
            }
            #pragma unroll
            for (int m = 16; m > 0; m >>= 1) {
                #pragma unroll
                for (int j = 0; j < 16; j++) {
                    s[j] += __shfl_xor_sync(0xffffffff, s[j], m);
                    q[j] += __shfl_xor_sync(0xffffffff, q[j], m);
                }
            }
            #pragma unroll
            for (int j = 0; j < 16; j++) {
                float mu  = s[j] * (1.f / 64.f);
                float var = q[j] * (1.f / 64.f) - mu * mu;
                float inv = rsqrtf(var + LN_EPS);
                o0[j] = fmaxf(fmaf((o0[j] - mu) * inv, p0w, p0b), 0.f);
                o1[j] = fmaxf(fmaf((o1[j] - mu) * inv, p1w, p1b), 0.f);
            }
        }

        // ---- GEMM2 ----
        __syncwarp();
        shbA[w][l]      = make_ulonglong2(pk(o0[0],  o0[1]),  pk(o0[2],  o0[3]));
        shbB[w][l]      = make_ulonglong2(pk(o0[4],  o0[5]),  pk(o0[6],  o0[7]));
        shbC[w][l]      = make_ulonglong2(pk(o0[8],  o0[9]),  pk(o0[10], o0[11]));
        shbD[w][l]      = make_ulonglong2(pk(o0[12], o0[13]), pk(o0[14], o0[15]));
        shbA[w][l + 32] = make_ulonglong2(pk(o1[0],  o1[1]),  pk(o1[2],  o1[3]));
        shbB[w][l + 32] = make_ulonglong2(pk(o1[4],  o1[5]),  pk(o1[6],  o1[7]));
        shbC[w][l + 32] = make_ulonglong2(pk(o1[8],  o1[9]),  pk(o1[10], o1[11]));
        shbD[w][l + 32] = make_ulonglong2(pk(o1[12], o1[13]), pk(o1[14], o1[15]));
        __syncwarp();
        #pragma unroll
        for (int i = 0; i < 8; i++) { accL[i] = Z; accH[i] = Z; }
        #pragma unroll
        for (int k = 0; k < 64; k++) {
            ulonglong2 hA = shbA[w][k];
            ulonglong2 hB = shbB[w][k];
            ulonglong2 hC = shbC[w][k];
            ulonglong2 hD = shbD[w][k];
            unsigned long long wxx = sW1x[k * 32 + l];
            unsigned long long wyy = sW1y[k * 32 + l];
            accL[0] = f2fma(hA.x, wxx, accL[0]); accH[0] = f2fma(hA.x, wyy, accH[0]);
            accL[1] = f2fma(hA.y, wxx, accL[1]); accH[1] = f2fma(hA.y, wyy, accH[1]);
            accL[2] = f2fma(hB.x, wxx, accL[2]); accH[2] = f2fma(hB.x, wyy, accH[2]);
            accL[3] = f2fma(hB.y, wxx, accL[3]); accH[3] = f2fma(hB.y, wyy, accH[3]);
            accL[4] = f2fma(hC.x, wxx, accL[4]); accH[4] = f2fma(hC.x, wyy, accH[4]);
            accL[5] = f2fma(hC.y, wxx, accL[5]); accH[5] = f2fma(hC.y, wyy, accH[5]);
            accL[6] = f2fma(hD.x, wxx, accL[6]); accH[6] = f2fma(hD.x, wyy, accH[6]);
            accL[7] = f2fma(hD.y, wxx, accL[7]); accH[7] = f2fma(hD.y, wyy, accH[7]);
        }
        float r0[16], r1[16];
        #pragma unroll
        for (int i = 0; i < 8; i++) {
            upk(accL[i], r0[2 * i], r0[2 * i + 1]);
            upk(accH[i], r1[2 * i], r1[2 * i + 1]);
        }

        // ---- LN1 + ReLU (16 nodes) ----
        {
            float s[16], q[16];
            #pragma unroll
            for (int j = 0; j < 16; j++) {
                s[j] = r0[j] + r1[j];
                q[j] = r0[j] * r0[j] + r1[j] * r1[j];
            }
            #pragma unroll
            for (int m = 16; m > 0; m >>= 1) {
                #pragma unroll
                for (int j = 0; j < 16; j++) {
                    s[j] += __shfl_xor_sync(0xffffffff, s[j], m);
                    q[j] += __shfl_xor_sync(0xffffffff, q[j], m);
                }
            }
            #pragma unroll
            for (int j = 0; j < 16; j++) {
                float mu  = s[j] * (1.f / 64.f);
                float var = q[j] * (1.f / 64.f) - mu * mu;
                float inv = rsqrtf(var + LN_EPS);
                r0[j] = fmaxf(fmaf((r0[j] - mu) * inv, q0w, q0b), 0.f);
                r1[j] = fmaxf(fmaf((r1[j] - mu) * inv, q1w, q1b), 0.f);
            }
        }

        // ---- store + GraphNorm partials ----
        #pragma unroll
        for (int j = 0; j < 16; j++) {
            int n = nbase + j;
            if (n < N) {
                long long b = (long long)n * C;
                h2[b + l]      = r0[j];
                h2[b + 32 + l] = r1[j];
                accS1_0 += r0[j];          accS1_1 += r1[j];
                accS2_0 += r0[j] * r0[j];  accS2_1 += r1[j] * r1[j];
            }
        }
        __syncwarp();
    }

    // Stats reduction staged into aliased smem region (main loop done).
    __syncthreads();
    if (tid < 128) sS[tid] = 0.f;
    __syncthreads();
    atomicAdd(&sS[l],           accS1_0);
    atomicAdd(&sS[l + 32],      accS1_1);
    atomicAdd(&sS[64 + l],      accS2_0);
    atomicAdd(&sS[64 + l + 32], accS2_1);
    __syncthreads();
    if (tid < 64)       atomicAdd(&S1[tid], sS[tid]);
    else if (tid < 128) atomicAdd(&S2[tid - 64], sS[tid]);
}

// ---------------------------------------------------------------------------
// K3: fused stats finalize + elementwise apply  out = A[c]*h + B[c]
//   Two independent float4 per thread (coalesced), no loop.
// ---------------------------------------------------------------------------
__global__ __launch_bounds__(256) void k_apply(
        const float4* __restrict__ h4,
        const float* __restrict__ S1, const float* __restrict__ S2,
        const float* __restrict__ gw, const float* __restrict__ gb,
        const float* __restrict__ ga,
        float4* __restrict__ out4, long long n4, float invN) {
    __shared__ float sA[64], sB[64];
    if (threadIdx.x < 64) {
        int c = threadIdx.x;
        float m  = S1[c] * invN;
        float e2 = S2[c] * invN;
        float a  = ga[c];
        float var = e2 - 2.f * a * m * m + a * a * m * m;
        float Ac  = gw[c] * rsqrtf(var + GN_EPS);
        sA[c] = Ac;
        sB[c] = gb[c] - Ac * a * m;
    }
    __syncthreads();

    long long i0 = (long long)blockIdx.x * 512 + threadIdx.x;
    long long i1 = i0 + 256;
    if (i0 < n4) {
        int c = (int)((i0 * 4) & 63);
        float4 v = h4[i0];
        v.x = fmaf(sA[c + 0], v.x, sB[c + 0]);
        v.y = fmaf(sA[c + 1], v.y, sB[c + 1]);
        v.z = fmaf(sA[c + 2], v.z, sB[c + 2]);
        v.w = fmaf(sA[c + 3], v.w, sB[c + 3]);
        out4[i0] = v;
    }
    if (i1 < n4) {
        int c = (int)((i1 * 4) & 63);
        float4 v = h4[i1];
        v.x = fmaf(sA[c + 0], v.x, sB[c + 0]);
        v.y = fmaf(sA[c + 1], v.y, sB[c + 1]);
        v.z = fmaf(sA[c + 2], v.z, sB[c + 2]);
        v.w = fmaf(sA[c + 3], v.w, sB[c + 3]);
        out4[i1] = v;
    }
}

// ---------------------------------------------------------------------------
extern "C" void kernel_launch(void* const* d_in, const int* in_sizes, int n_in,
                              void* d_out, int out_size) {
    const float*     x    = (const float*)d_in[0];
    const long long* ei   = (const long long*)d_in[1];
    const float*     W0   = (const float*)d_in[2];
    const float*     ln0w = (const float*)d_in[3];
    const float*     ln0b = (const float*)d_in[4];
    const float*     W1   = (const float*)d_in[5];
    const float*     ln1w = (const float*)d_in[6];
    const float*     ln1b = (const float*)d_in[7];
    const float*     gnw  = (const float*)d_in[8];
    const float*     gnb  = (const float*)d_in[9];
    const float*     gna  = (const float*)d_in[10];
    float*           out  = (float*)d_out;

    int N = in_sizes[0] / C;
    int E = in_sizes[1] / 2;
    if (N > MAXN) N = MAXN;
    if (E > MAXE) E = MAXE;

    float *agg, *h2, *S1, *S2;
    cudaGetSymbolAddress((void**)&agg, g_agg);
    cudaGetSymbolAddress((void**)&h2,  g_h2);
    cudaGetSymbolAddress((void**)&S1,  g_S1);
    cudaGetSymbolAddress((void**)&S2,  g_S2);

    long long nelem = (long long)N * C;
    long long n4 = nelem / 4;
    const int MLP_SMEM = 96 * 1024;
    static bool attr_set = false;
    if (!attr_set) {
        cudaFuncSetAttribute(k_mlp, cudaFuncAttributeMaxDynamicSharedMemorySize,
                             MLP_SMEM);
        attr_set = true;
    }

    // K0: agg = x, zero stats (2 float4/thread, one-shot)
    {
        int blocks = (int)((n4 + 511) / 512);
        k_init<<<blocks, 256>>>((const float4*)x, (float4*)agg, n4, S1, S2);
    }
    // K1: scatter-add (16 threads/edge, vector atomics)
    {
        long long threads = (long long)E * 16;
        int blocks = (int)((threads + 255) / 256);
        k_scatter<<<blocks, 256>>>(x, ei, agg, E, N);
    }
    // K2: MLP + partial GraphNorm stats (persistent, 16 nodes/warp, f32x2,
    //     pre-duplicated weights)
    {
        int groups = (N + 127) / 128;
        int blocks = groups < 296 ? groups : 296;
        k_mlp<<<blocks, 256, MLP_SMEM>>>(agg, W0, ln0w, ln0b, W1, ln1w, ln1b,
                                         h2, S1, S2, N);
    }
    // K3: fused stats + apply (2 float4/thread, one-shot)
    {
        int blocks = (int)((n4 + 511) / 512);
        k_apply<<<blocks, 256>>>((const float4*)h2, S1, S2, gnw, gnb, gna,
                                 (float4*)out, n4, 1.0f / (float)N);
    }
}

// round 15
// speedup vs baseline: 1.0639x; 1.0639x over previous
#include <cuda_runtime.h>

#define C 64
#define MAXN 50000
#define MAXE 800000
#define LN_EPS 1e-5f
#define GN_EPS 1e-5f

// Scratch (no allocs allowed)
__device__ float g_agg[(size_t)MAXN * C];
__device__ float g_h2[(size_t)MAXN * C];
__device__ float g_S1[C];
__device__ float g_S2[C];
__device__ int   g_ei64;   // 1 if edge_index is int64, 0 if int32

// ---------------------------------------------------------------------------
// f32x2 packed-FMA helpers (sm_100+)
// ---------------------------------------------------------------------------
__device__ __forceinline__ unsigned long long pk(float x, float y) {
    unsigned long long r;
    asm("mov.b64 %0, {%1, %2};" : "=l"(r) : "f"(x), "f"(y));
    return r;
}
__device__ __forceinline__ void upk(unsigned long long p, float& x, float& y) {
    asm("mov.b64 {%0, %1}, %2;" : "=f"(x), "=f"(y) : "l"(p));
}
__device__ __forceinline__ unsigned long long f2fma(unsigned long long a,
                                                    unsigned long long b,
                                                    unsigned long long c) {
    unsigned long long d;
    asm("fma.rn.f32x2 %0, %1, %2, %3;" : "=l"(d) : "l"(a), "l"(b), "l"(c));
    return d;
}

// ---------------------------------------------------------------------------
// K0: agg = x (GIN self term), zero stats, sniff edge dtype once.
//   (JAX x64-disable silently narrows int64 -> int32; int32 misread as int64
//    is astronomically out of [0,N) range.)
// ---------------------------------------------------------------------------
__global__ void k_init(const float4* __restrict__ x4, float4* __restrict__ agg4,
                       long long n4, float* s1, float* s2,
                       const long long* __restrict__ ei, int N) {
    long long i = (long long)blockIdx.x * blockDim.x + threadIdx.x;
    if (i < n4) agg4[i] = x4[i];
    if (i < C) { s1[i] = 0.f; s2[i] = 0.f; }
    if (i == 0) {
        bool ok = true;
        #pragma unroll
        for (int j = 0; j < 4; j++) {
            long long v = __ldg(ei + j);
            ok = ok && (v >= 0) && (v < (long long)N);
        }
        g_ei64 = ok ? 1 : 0;
    }
}

// ---------------------------------------------------------------------------
// K1: scatter-add   agg[dst] += x[src]   (16 threads/edge, float4 vector red)
// ---------------------------------------------------------------------------
__global__ void k_scatter(const float* __restrict__ x,
                          const long long* __restrict__ ei,
                          float* __restrict__ agg, int E, int N) {
    long long tid = (long long)blockIdx.x * blockDim.x + threadIdx.x;
    int e = (int)(tid >> 4);
    if (e >= E) return;
    int g = (int)(tid & 15);

    int s, d;
    if (g_ei64) {
        s = (int)__ldg(ei + e);
        d = (int)__ldg(ei + (long long)E + e);
    } else {
        const int* ei32 = (const int*)ei;
        s = __ldg(ei32 + e);
        d = __ldg(ei32 + (long long)E + e);
    }
    if ((unsigned)s >= (unsigned)N || (unsigned)d >= (unsigned)N) return;

    float4 v = __ldg((const float4*)(x + (long long)s * C) + g);
    float4* a4 = (float4*)(agg + (long long)d * C) + g;
    atomicAdd(a4, v);   // RED.E.ADD.V4.F32
}

// ---------------------------------------------------------------------------
// K2: MLP, 16 nodes/warp, f32x2 packed FMA, dynamic 64KB smem, persistent,
//     fused GN partials. Per k-iter: 4 broadcast LDS.128 + 1 LDS.64 + 16 FFMA2.
// ---------------------------------------------------------------------------
__global__ __launch_bounds__(256, 2) void k_mlp(
    const float* __restrict__ agg,
    const float* __restrict__ W0, const float* __restrict__ ln0w, const float* __restrict__ ln0b,
    const float* __restrict__ W1, const float* __restrict__ ln1w, const float* __restrict__ ln1b,
    float* __restrict__ h2, float* __restrict__ S1, float* __restrict__ S2, int N) {

    extern __shared__ char dsm[];
    // layout: W0 16KB | W1 16KB | shbA 8KB | shbB 8KB | shbC 8KB | shbD 8KB
    float2* sW0v = (float2*)dsm;                         // [64*32]
    float2* sW1v = (float2*)(dsm + 16384);               // [64*32]
    ulonglong2 (*shbA)[64] = (ulonglong2(*)[64])(dsm + 32768);
    ulonglong2 (*shbB)[64] = (ulonglong2(*)[64])(dsm + 40960);
    ulonglong2 (*shbC)[64] = (ulonglong2(*)[64])(dsm + 49152);
    ulonglong2 (*shbD)[64] = (ulonglong2(*)[64])(dsm + 57344);
    float* sS = (float*)(dsm + 32768);   // aliased stats staging (post-loop)

    int tid = threadIdx.x;
    for (int i = tid; i < 2048; i += 256) {
        int k = i >> 5, l = i & 31;
        sW0v[i] = make_float2(W0[l * 64 + k], W0[(l + 32) * 64 + k]);
        sW1v[i] = make_float2(W1[l * 64 + k], W1[(l + 32) * 64 + k]);
    }
    __syncthreads();

    int w = tid >> 5, l = tid & 31;
    float p0w = __ldg(ln0w + l),      p0b = __ldg(ln0b + l);
    float p1w = __ldg(ln0w + l + 32), p1b = __ldg(ln0b + l + 32);
    float q0w = __ldg(ln1w + l),      q0b = __ldg(ln1b + l);
    float q1w = __ldg(ln1w + l + 32), q1b = __ldg(ln1b + l + 32);

    float accS1_0 = 0.f, accS1_1 = 0.f, accS2_0 = 0.f, accS2_1 = 0.f;
    const unsigned long long Z = 0ull;

    int groups = (N + 127) >> 7;         // 128 nodes per block-iteration
    for (int gi = blockIdx.x; gi < groups; gi += gridDim.x) {
        int nbase = gi * 128 + w * 16;

        // ---- load h (16 nodes) + stage into shared ----
        {
            float h0[16], h1[16];
            #pragma unroll
            for (int j = 0; j < 16; j++) {
                int n = nbase + j;
                if (n < N) {
                    long long b = (long long)n * C;
                    h0[j] = agg[b + l];
                    h1[j] = agg[b + 32 + l];
                } else { h0[j] = 0.f; h1[j] = 0.f; }
            }
            shbA[w][l]      = make_ulonglong2(pk(h0[0],  h0[1]),  pk(h0[2],  h0[3]));
            shbB[w][l]      = make_ulonglong2(pk(h0[4],  h0[5]),  pk(h0[6],  h0[7]));
            shbC[w][l]      = make_ulonglong2(pk(h0[8],  h0[9]),  pk(h0[10], h0[11]));
            shbD[w][l]      = make_ulonglong2(pk(h0[12], h0[13]), pk(h0[14], h0[15]));
            shbA[w][l + 32] = make_ulonglong2(pk(h1[0],  h1[1]),  pk(h1[2],  h1[3]));
            shbB[w][l + 32] = make_ulonglong2(pk(h1[4],  h1[5]),  pk(h1[6],  h1[7]));
            shbC[w][l + 32] = make_ulonglong2(pk(h1[8],  h1[9]),  pk(h1[10], h1[11]));
            shbD[w][l + 32] = make_ulonglong2(pk(h1[12], h1[13]), pk(h1[14], h1[15]));
        }
        __syncwarp();

        // ---- GEMM1 ----
        unsigned long long accL[8], accH[8];
        #pragma unroll
        for (int i = 0; i < 8; i++) { accL[i] = Z; accH[i] = Z; }
        #pragma unroll
        for (int k = 0; k < 64; k++) {
            ulonglong2 hA = shbA[w][k];
            ulonglong2 hB = shbB[w][k];
            ulonglong2 hC = shbC[w][k];
            ulonglong2 hD = shbD[w][k];
            float2 wv = sW0v[k * 32 + l];
            unsigned long long wxx = pk(wv.x, wv.x);
            unsigned long long wyy = pk(wv.y, wv.y);
            accL[0] = f2fma(hA.x, wxx, accL[0]); accH[0] = f2fma(hA.x, wyy, accH[0]);
            accL[1] = f2fma(hA.y, wxx, accL[1]); accH[1] = f2fma(hA.y, wyy, accH[1]);
            accL[2] = f2fma(hB.x, wxx, accL[2]); accH[2] = f2fma(hB.x, wyy, accH[2]);
            accL[3] = f2fma(hB.y, wxx, accL[3]); accH[3] = f2fma(hB.y, wyy, accH[3]);
            accL[4] = f2fma(hC.x, wxx, accL[4]); accH[4] = f2fma(hC.x, wyy, accH[4]);
            accL[5] = f2fma(hC.y, wxx, accL[5]); accH[5] = f2fma(hC.y, wyy, accH[5]);
            accL[6] = f2fma(hD.x, wxx, accL[6]); accH[6] = f2fma(hD.x, wyy, accH[6]);
            accL[7] = f2fma(hD.y, wxx, accL[7]); accH[7] = f2fma(hD.y, wyy, accH[7]);
        }
        float o0[16], o1[16];
        #pragma unroll
        for (int i = 0; i < 8; i++) {
            upk(accL[i], o0[2 * i], o0[2 * i + 1]);
            upk(accH[i], o1[2 * i], o1[2 * i + 1]);
        }

        // ---- LN0 + ReLU (16 nodes) ----
        {
            float s[16], q[16];
            #pragma unroll
            for (int j = 0; j < 16; j++) {
                s[j] = o0[j] + o1[j];
                q[j] = o0[j] * o0[j] + o1[j] * o1[j];
            }
            #pragma unroll
            for (int m = 16; m > 0; m >>= 1) {
                #pragma unroll
                for (int j = 0; j < 16; j++) {
                    s[j] += __shfl_xor_sync(0xffffffff, s[j], m);
                    q[j] += __shfl_xor_sync(0xffffffff, q[j], m);
                }
            }
            #pragma unroll
            for (int j = 0; j < 16; j++) {
                float mu  = s[j] * (1.f / 64.f);
                float var = q[j] * (1.f / 64.f) - mu * mu;
                float inv = rsqrtf(var + LN_EPS);
                o0[j] = fmaxf(fmaf((o0[j] - mu) * inv, p0w, p0b), 0.f);
                o1[j] = fmaxf(fmaf((o1[j] - mu) * inv, p1w, p1b), 0.f);
            }
        }

        // ---- GEMM2 ----
        __syncwarp();
        shbA[w][l]      = make_ulonglong2(pk(o0[0],  o0[1]),  pk(o0[2],  o0[3]));
        shbB[w][l]      = make_ulonglong2(pk(o0[4],  o0[5]),  pk(o0[6],  o0[7]));
        shbC[w][l]      = make_ulonglong2(pk(o0[8],  o0[9]),  pk(o0[10], o0[11]));
        shbD[w][l]      = make_ulonglong2(pk(o0[12], o0[13]), pk(o0[14], o0[15]));
        shbA[w][l + 32] = make_ulonglong2(pk(o1[0],  o1[1]),  pk(o1[2],  o1[3]));
        shbB[w][l + 32] = make_ulonglong2(pk(o1[4],  o1[5]),  pk(o1[6],  o1[7]));
        shbC[w][l + 32] = make_ulonglong2(pk(o1[8],  o1[9]),  pk(o1[10], o1[11]));
        shbD[w][l + 32] = make_ulonglong2(pk(o1[12], o1[13]), pk(o1[14], o1[15]));
        __syncwarp();
        #pragma unroll
        for (int i = 0; i < 8; i++) { accL[i] = Z; accH[i] = Z; }
        #pragma unroll
        for (int k = 0; k < 64; k++) {
            ulonglong2 hA = shbA[w][k];
            ulonglong2 hB = shbB[w][k];
            ulonglong2 hC = shbC[w][k];
            ulonglong2 hD = shbD[w][k];
            float2 wv = sW1v[k * 32 + l];
            unsigned long long wxx = pk(wv.x, wv.x);
            unsigned long long wyy = pk(wv.y, wv.y);
            accL[0] = f2fma(hA.x, wxx, accL[0]); accH[0] = f2fma(hA.x, wyy, accH[0]);
            accL[1] = f2fma(hA.y, wxx, accL[1]); accH[1] = f2fma(hA.y, wyy, accH[1]);
            accL[2] = f2fma(hB.x, wxx, accL[2]); accH[2] = f2fma(hB.x, wyy, accH[2]);
            accL[3] = f2fma(hB.y, wxx, accL[3]); accH[3] = f2fma(hB.y, wyy, accH[3]);
            accL[4] = f2fma(hC.x, wxx, accL[4]); accH[4] = f2fma(hC.x, wyy, accH[4]);
            accL[5] = f2fma(hC.y, wxx, accL[5]); accH[5] = f2fma(hC.y, wyy, accH[5]);
            accL[6] = f2fma(hD.x, wxx, accL[6]); accH[6] = f2fma(hD.x, wyy, accH[6]);
            accL[7] = f2fma(hD.y, wxx, accL[7]); accH[7] = f2fma(hD.y, wyy, accH[7]);
        }
        float r0[16], r1[16];
        #pragma unroll
        for (int i = 0; i < 8; i++) {
            upk(accL[i], r0[2 * i], r0[2 * i + 1]);
            upk(accH[i], r1[2 * i], r1[2 * i + 1]);
        }

        // ---- LN1 + ReLU (16 nodes) ----
        {
            float s[16], q[16];
            #pragma unroll
            for (int j = 0; j < 16; j++) {
                s[j] = r0[j] + r1[j];
                q[j] = r0[j] * r0[j] + r1[j] * r1[j];
            }
            #pragma unroll
            for (int m = 16; m > 0; m >>= 1) {
                #pragma unroll
                for (int j = 0; j < 16; j++) {
                    s[j] += __shfl_xor_sync(0xffffffff, s[j], m);
                    q[j] += __shfl_xor_sync(0xffffffff, q[j], m);
                }
            }
            #pragma unroll
            for (int j = 0; j < 16; j++) {
                float mu  = s[j] * (1.f / 64.f);
                float var = q[j] * (1.f / 64.f) - mu * mu;
                float inv = rsqrtf(var + LN_EPS);
                r0[j] = fmaxf(fmaf((r0[j] - mu) * inv, q0w, q0b), 0.f);
                r1[j] = fmaxf(fmaf((r1[j] - mu) * inv, q1w, q1b), 0.f);
            }
        }

        // ---- store + GraphNorm partials ----
        #pragma unroll
        for (int j = 0; j < 16; j++) {
            int n = nbase + j;
            if (n < N) {
                long long b = (long long)n * C;
                h2[b + l]      = r0[j];
                h2[b + 32 + l] = r1[j];
                accS1_0 += r0[j];          accS1_1 += r1[j];
                accS2_0 += r0[j] * r0[j];  accS2_1 += r1[j] * r1[j];
            }
        }
        __syncwarp();
    }

    // Stats reduction staged into shbA region (main loop done).
    __syncthreads();
    if (tid < 128) sS[tid] = 0.f;
    __syncthreads();
    atomicAdd(&sS[l],           accS1_0);
    atomicAdd(&sS[l + 32],      accS1_1);
    atomicAdd(&sS[64 + l],      accS2_0);
    atomicAdd(&sS[64 + l + 32], accS2_1);
    __syncthreads();
    if (tid < 64)       atomicAdd(&S1[tid], sS[tid]);
    else if (tid < 128) atomicAdd(&S2[tid - 64], sS[tid]);
}

// ---------------------------------------------------------------------------
// K3: fused stats finalize + elementwise apply  out = A[c]*h + B[c]
//   One float4 per thread (no loop); 4-channel group known per thread.
// ---------------------------------------------------------------------------
__global__ __launch_bounds__(256) void k_apply(
        const float4* __restrict__ h4,
        const float* __restrict__ S1, const float* __restrict__ S2,
        const float* __restrict__ gw, const float* __restrict__ gb,
        const float* __restrict__ ga,
        float4* __restrict__ out4, long long n4, float invN) {
    __shared__ float sA[64], sB[64];
    if (threadIdx.x < 64) {
        int c = threadIdx.x;
        float m  = S1[c] * invN;
        float e2 = S2[c] * invN;
        float a  = ga[c];
        float var = e2 - 2.f * a * m * m + a * a * m * m;
        float Ac  = gw[c] * rsqrtf(var + GN_EPS);
        sA[c] = Ac;
        sB[c] = gb[c] - Ac * a * m;
    }
    __syncthreads();

    long long i = (long long)blockIdx.x * blockDim.x + threadIdx.x;
    if (i >= n4) return;
    int c = (int)((i * 4) & 63);
    float4 v = h4[i];
    v.x = fmaf(sA[c + 0], v.x, sB[c + 0]);
    v.y = fmaf(sA[c + 1], v.y, sB[c + 1]);
    v.z = fmaf(sA[c + 2], v.z, sB[c + 2]);
    v.w = fmaf(sA[c + 3], v.w, sB[c + 3]);
    out4[i] = v;
}

// ---------------------------------------------------------------------------
extern "C" void kernel_launch(void* const* d_in, const int* in_sizes, int n_in,
                              void* d_out, int out_size) {
    const float*     x    = (const float*)d_in[0];
    const long long* ei   = (const long long*)d_in[1];
    const float*     W0   = (const float*)d_in[2];
    const float*     ln0w = (const float*)d_in[3];
    const float*     ln0b = (const float*)d_in[4];
    const float*     W1   = (const float*)d_in[5];
    const float*     ln1w = (const float*)d_in[6];
    const float*     ln1b = (const float*)d_in[7];
    const float*     gnw  = (const float*)d_in[8];
    const float*     gnb  = (const float*)d_in[9];
    const float*     gna  = (const float*)d_in[10];
    float*           out  = (float*)d_out;

    int N = in_sizes[0] / C;
    int E = in_sizes[1] / 2;
    if (N > MAXN) N = MAXN;
    if (E > MAXE) E = MAXE;

    float *agg, *h2, *S1, *S2;
    cudaGetSymbolAddress((void**)&agg, g_agg);
    cudaGetSymbolAddress((void**)&h2,  g_h2);
    cudaGetSymbolAddress((void**)&S1,  g_S1);
    cudaGetSymbolAddress((void**)&S2,  g_S2);

    long long nelem = (long long)N * C;
    long long n4 = nelem / 4;
    const int MLP_SMEM = 64 * 1024;
    static bool attr_set = false;
    if (!attr_set) {
        cudaFuncSetAttribute(k_mlp, cudaFuncAttributeMaxDynamicSharedMemorySize,
                             MLP_SMEM);
        attr_set = true;
    }

    // K0: agg = x, zero stats, sniff edge dtype (one-shot)
    {
        int blocks = (int)((n4 + 255) / 256);
        k_init<<<blocks, 256>>>((const float4*)x, (float4*)agg, n4, S1, S2,
                                ei, N);
    }
    // K1: scatter-add (16 threads/edge, vector atomics)
    {
        long long threads = (long long)E * 16;
        int blocks = (int)((threads + 255) / 256);
        k_scatter<<<blocks, 256>>>(x, ei, agg, E, N);
    }
    // K2: MLP + partial GraphNorm stats (persistent, 16 nodes/warp, f32x2)
    {
        int groups = (N + 127) / 128;
        int blocks = groups < 296 ? groups : 296;
        k_mlp<<<blocks, 256, MLP_SMEM>>>(agg, W0, ln0w, ln0b, W1, ln1w, ln1b,
                                         h2, S1, S2, N);
    }
    // K3: fused stats + apply (one-shot)
    {
        int blocks = (int)((n4 + 255) / 256);
        k_apply<<<blocks, 256>>>((const float4*)h2, S1, S2, gnw, gnb, gna,
                                 (float4*)out, n4, 1.0f / (float)N);
    }
}